// round 2
// baseline (speedup 1.0000x reference)
#include <cuda_runtime.h>

#define N_TOT  8192
#define D_DIM  256
#define B_HALF 4096
#define TILE   64
#define KC     32
#define AS     68                  // padded smem row stride (floats), keeps 16B align
#define BS     68
#define NJT    (N_TOT / TILE)      // 128 column tiles
#define NKS    (D_DIM / KC)        // 8 k-stages per tile

// -------- device scratch (no allocations allowed) --------
__device__ __align__(16) float g_buf[N_TOT * D_DIM];   // normalized features (8 MB, L2-resident)
__device__ int   lab_buf[N_TOT];
__device__ float rowsum_all[N_TOT];
__device__ float rowsum_pos[N_TOT];

// -------- Blackwell packed-fp32 helpers --------
static __device__ __forceinline__ unsigned long long ffma2(unsigned long long a,
                                                           unsigned long long b,
                                                           unsigned long long c) {
    unsigned long long d;
    asm("fma.rn.f32x2 %0, %1, %2, %3;" : "=l"(d) : "l"(a), "l"(b), "l"(c));
    return d;
}
static __device__ __forceinline__ unsigned long long bcast2(float x) {
    unsigned long long d;
    asm("mov.b64 %0, {%1, %1};" : "=l"(d) : "r"(__float_as_uint(x)));
    return d;
}
static __device__ __forceinline__ float ex2f(float x) {
    float r; asm("ex2.approx.ftz.f32 %0, %1;" : "=f"(r) : "f"(x)); return r;
}

// ============================================================================
// Kernel 1: L2-normalize rows of [features; pos_features], convert labels.
// One warp per row (256 elems = 2 float4 per lane).
// ============================================================================
__global__ void prep_kernel(const float* __restrict__ feats,
                            const float* __restrict__ posf,
                            const int* __restrict__ labels) {
    int row  = blockIdx.x * 8 + (threadIdx.x >> 5);
    int lane = threadIdx.x & 31;
    const float* src = (row < B_HALF) ? (feats + (size_t)row * D_DIM)
                                      : (posf + (size_t)(row - B_HALF) * D_DIM);
    const float4* s4 = reinterpret_cast<const float4*>(src);
    float4 v0 = s4[lane];
    float4 v1 = s4[lane + 32];
    float ss = v0.x*v0.x + v0.y*v0.y + v0.z*v0.z + v0.w*v0.w
             + v1.x*v1.x + v1.y*v1.y + v1.z*v1.z + v1.w*v1.w;
    #pragma unroll
    for (int off = 16; off > 0; off >>= 1)
        ss += __shfl_xor_sync(0xffffffffu, ss, off);
    float inv = rsqrtf(ss);
    float4* d4 = reinterpret_cast<float4*>(g_buf + (size_t)row * D_DIM);
    v0.x *= inv; v0.y *= inv; v0.z *= inv; v0.w *= inv;
    v1.x *= inv; v1.y *= inv; v1.z *= inv; v1.w *= inv;
    d4[lane]      = v0;
    d4[lane + 32] = v1;
    if (lane == 0)
        lab_buf[row] = labels[(row < B_HALF) ? row : row - B_HALF];
}

// ============================================================================
// Kernel 2: main fused GEMM + exp + masked row sums.
// Grid = 128 CTAs, each owns 64 rows; loops over all 128 column tiles.
// A tile (64x256) lives fully in SMEM (k-major); B slabs (64x32) double-buffered.
// Thread tile 4x4, accumulated as fp32x2 row-pairs via fma.rn.f32x2.
// ============================================================================
__global__ void __launch_bounds__(256, 1) milnce_main_kernel() {
    extern __shared__ float smem[];
    float* A_t = smem;                       // [D_DIM][AS]
    float* Bst = smem + D_DIM * AS;          // [2][KC][BS]

    const int tid = threadIdx.x;
    const int i0  = blockIdx.x * TILE;
    const int tr  = tid >> 4;                // 0..15, 4 rows each
    const int tc  = tid & 15;                // 0..15, 4 cols each

    // B-slab load mapping: 2 float4 per thread per stage
    const int br  = tid >> 3;                // row within slab (0..31), +32 for 2nd vec
    const int bkv = tid & 7;                 // float4 index within 32-float k-slab

    const float4* gb4 = reinterpret_cast<const float4*>(g_buf);

    // prologue: issue LDG for B stage (jt=0, ks=0) early
    float4 p0 = gb4[(0 * TILE + br) * (D_DIM / 4) + 0 * 8 + bkv];
    float4 p1 = gb4[(0 * TILE + br + 32) * (D_DIM / 4) + 0 * 8 + bkv];

    // stage full A tile (64 rows x 256 k) into SMEM, k-major
    #pragma unroll 1
    for (int v = tid; v < TILE * (D_DIM / 4); v += 256) {
        int r  = v >> 6;                     // 64 float4 per row
        int kv = v & 63;
        float4 a = gb4[(i0 + r) * (D_DIM / 4) + kv];
        A_t[(kv * 4 + 0) * AS + r] = a.x;
        A_t[(kv * 4 + 1) * AS + r] = a.y;
        A_t[(kv * 4 + 2) * AS + r] = a.z;
        A_t[(kv * 4 + 3) * AS + r] = a.w;
    }

    int labi[4];
    #pragma unroll
    for (int r = 0; r < 4; r++) labi[r] = lab_buf[i0 + tr * 4 + r];

    float sall[4] = {0.f, 0.f, 0.f, 0.f};
    float spos[4] = {0.f, 0.f, 0.f, 0.f};

    // store B stage 0 into buffer 0, then sync (also covers A_t)
    {
        float* Bp = Bst;
        Bp[(bkv * 4 + 0) * BS + br] = p0.x;
        Bp[(bkv * 4 + 1) * BS + br] = p0.y;
        Bp[(bkv * 4 + 2) * BS + br] = p0.z;
        Bp[(bkv * 4 + 3) * BS + br] = p0.w;
        Bp[(bkv * 4 + 0) * BS + br + 32] = p1.x;
        Bp[(bkv * 4 + 1) * BS + br + 32] = p1.y;
        Bp[(bkv * 4 + 2) * BS + br + 32] = p1.z;
        Bp[(bkv * 4 + 3) * BS + br + 32] = p1.w;
    }
    __syncthreads();

    #pragma unroll 1
    for (int jt = 0; jt < NJT; jt++) {
        const int j0 = jt * TILE;

        unsigned long long acc[2][4];
        #pragma unroll
        for (int rp = 0; rp < 2; rp++)
            #pragma unroll
            for (int c = 0; c < 4; c++) acc[rp][c] = 0ull;

        // prefetch column labels (consumed in epilogue, fully hidden)
        int labc[4];
        #pragma unroll
        for (int c = 0; c < 4; c++) labc[c] = lab_buf[j0 + tc * 4 + c];

        #pragma unroll 1
        for (int ks = 0; ks < NKS; ks++) {
            const int buf = ks & 1;
            const bool has_next = (jt * NKS + ks + 1) < (NJT * NKS);
            float4 n0, n1;
            if (has_next) {
                const int njt = (ks == NKS - 1) ? jt + 1 : jt;
                const int nks = (ks == NKS - 1) ? 0 : ks + 1;
                const int nj0 = njt * TILE;
                n0 = gb4[(nj0 + br) * (D_DIM / 4) + nks * 8 + bkv];
                n1 = gb4[(nj0 + br + 32) * (D_DIM / 4) + nks * 8 + bkv];
            }

            // compute 32 k-steps from current buffer
            const float* Ap = A_t + (ks * KC) * AS + tr * 4;
            const float* Bp = Bst + buf * (KC * BS) + tc * 4;
            #pragma unroll
            for (int kk = 0; kk < KC; kk++) {
                double2 av = *reinterpret_cast<const double2*>(Ap + kk * AS);
                float4  bv = *reinterpret_cast<const float4*>(Bp + kk * BS);
                unsigned long long a01 = __double_as_longlong(av.x);
                unsigned long long a23 = __double_as_longlong(av.y);
                unsigned long long b0 = bcast2(bv.x);
                unsigned long long b1 = bcast2(bv.y);
                unsigned long long b2 = bcast2(bv.z);
                unsigned long long b3 = bcast2(bv.w);
                acc[0][0] = ffma2(a01, b0, acc[0][0]);
                acc[1][0] = ffma2(a23, b0, acc[1][0]);
                acc[0][1] = ffma2(a01, b1, acc[0][1]);
                acc[1][1] = ffma2(a23, b1, acc[1][1]);
                acc[0][2] = ffma2(a01, b2, acc[0][2]);
                acc[1][2] = ffma2(a23, b2, acc[1][2]);
                acc[0][3] = ffma2(a01, b3, acc[0][3]);
                acc[1][3] = ffma2(a23, b3, acc[1][3]);
            }

            if (has_next) {
                float* Bn = Bst + (buf ^ 1) * (KC * BS);
                Bn[(bkv * 4 + 0) * BS + br] = n0.x;
                Bn[(bkv * 4 + 1) * BS + br] = n0.y;
                Bn[(bkv * 4 + 2) * BS + br] = n0.z;
                Bn[(bkv * 4 + 3) * BS + br] = n0.w;
                Bn[(bkv * 4 + 0) * BS + br + 32] = n1.x;
                Bn[(bkv * 4 + 1) * BS + br + 32] = n1.y;
                Bn[(bkv * 4 + 2) * BS + br + 32] = n1.z;
                Bn[(bkv * 4 + 3) * BS + br + 32] = n1.w;
            }
            __syncthreads();
        }

        // epilogue: exp + masked accumulation
        const float K_EXP = 14.426950408889634f;   // log2(e) / tau
        #pragma unroll
        for (int rp = 0; rp < 2; rp++) {
            #pragma unroll
            for (int c = 0; c < 4; c++) {
                unsigned int ulo, uhi;
                asm("mov.b64 {%0, %1}, %2;" : "=r"(ulo), "=r"(uhi) : "l"(acc[rp][c]));
                float zl = __uint_as_float(ulo);
                float zh = __uint_as_float(uhi);
                int gj  = j0 + tc * 4 + c;
                int r0  = rp * 2;
                int r1  = rp * 2 + 1;
                int gi0 = i0 + tr * 4 + r0;
                int gi1 = gi0 + 1;
                float el = ex2f(zl * K_EXP);
                float eh = ex2f(zh * K_EXP);
                if (gi0 != gj) {
                    sall[r0] += el;
                    if (labi[r0] == labc[c]) spos[r0] += el;
                }
                if (gi1 != gj) {
                    sall[r1] += eh;
                    if (labi[r1] == labc[c]) spos[r1] += eh;
                }
            }
        }
    }

    // reduce over the 16 column-threads sharing each row (xor<=8 stays in 16-lane half)
    #pragma unroll
    for (int r = 0; r < 4; r++) {
        #pragma unroll
        for (int off = 8; off > 0; off >>= 1) {
            sall[r] += __shfl_xor_sync(0xffffffffu, sall[r], off);
            spos[r] += __shfl_xor_sync(0xffffffffu, spos[r], off);
        }
    }
    if (tc == 0) {
        #pragma unroll
        for (int r = 0; r < 4; r++) {
            rowsum_all[i0 + tr * 4 + r] = sall[r];
            rowsum_pos[i0 + tr * 4 + r] = spos[r];
        }
    }
}

// ============================================================================
// Kernel 3: loss = sum_i log(S_all_i) - log(S_pos_i)
// ============================================================================
__global__ void finalize_kernel(float* __restrict__ out) {
    __shared__ float red[256];
    float s = 0.f;
    for (int i = threadIdx.x; i < N_TOT; i += 256)
        s += logf(rowsum_all[i]) - logf(rowsum_pos[i]);
    red[threadIdx.x] = s;
    __syncthreads();
    for (int o = 128; o > 0; o >>= 1) {
        if (threadIdx.x < o) red[threadIdx.x] += red[threadIdx.x + o];
        __syncthreads();
    }
    if (threadIdx.x == 0) out[0] = red[0];
}

// ============================================================================
extern "C" void kernel_launch(void* const* d_in, const int* in_sizes, int n_in,
                              void* d_out, int out_size) {
    const float* feats  = (const float*)d_in[0];
    const float* posf   = (const float*)d_in[1];
    const int*   labels = (const int*)d_in[2];

    prep_kernel<<<N_TOT / 8, 256>>>(feats, posf, labels);

    const int smem_bytes = (D_DIM * AS + 2 * KC * BS) * (int)sizeof(float); // 87040
    cudaFuncSetAttribute(milnce_main_kernel,
                         cudaFuncAttributeMaxDynamicSharedMemorySize, smem_bytes);
    milnce_main_kernel<<<NJT, 256, smem_bytes>>>();

    finalize_kernel<<<1, 256>>>((float*)d_out);
}

// round 4
// speedup vs baseline: 6.8623x; 6.8623x over previous
#include <cuda_runtime.h>
#include <cuda_bf16.h>
#include <cstdint>

#define N_TOT   8192
#define D_DIM   256
#define B_HALF  4096
#define TILE_M  128
#define TILE_N  128
#define NJ_HALF 32                 // column tiles per half
#define K_STEPS 16                 // 256 / 16

#define ROW_BYTES 528              // 264 bf16: pad to kill ldmatrix bank conflicts
#define A_OFF   0
#define B0_OFF  (TILE_M * ROW_BYTES)                 // 67584
#define B1_OFF  (B0_OFF + TILE_M * ROW_BYTES)        // 135168
#define RED_OFF (B1_OFF + TILE_M * ROW_BYTES)        // 202752
#define SMEM_TOTAL (RED_OFF + 128 * 4 * 2 * 4)       // + red buffers = 206848

// -------- device scratch --------
__device__ __align__(16) __nv_bfloat16 g_bf[N_TOT * D_DIM];   // normalized bf16 (4 MB)
__device__ int   lab_buf[N_TOT];
__device__ float part_all[2][N_TOT];
__device__ float part_pos[2][N_TOT];

// ======================= helpers =======================
static __device__ __forceinline__ uint32_t smem_u32(const void* p) {
    uint32_t a;
    asm("{ .reg .u64 t; cvta.to.shared.u64 t, %1; cvt.u32.u64 %0, t; }" : "=r"(a) : "l"(p));
    return a;
}
static __device__ __forceinline__ float ex2f(float x) {
    float r; asm("ex2.approx.ftz.f32 %0, %1;" : "=f"(r) : "f"(x)); return r;
}
static __device__ __forceinline__ uint32_t pack_bf2(float lo, float hi) {
    uint32_t r; asm("cvt.rn.bf16x2.f32 %0, %1, %2;" : "=r"(r) : "f"(hi), "f"(lo)); return r;
}
static __device__ __forceinline__ void cp16(uint32_t saddr, const void* g) {
    asm volatile("cp.async.cg.shared.global [%0], [%1], 16;" :: "r"(saddr), "l"(g) : "memory");
}
#define CP_COMMIT() asm volatile("cp.async.commit_group;" ::: "memory")
#define CP_WAIT(n)  asm volatile("cp.async.wait_group %0;" :: "n"(n) : "memory")

static __device__ __forceinline__ void ldsm_x4(uint32_t& r0, uint32_t& r1,
                                               uint32_t& r2, uint32_t& r3, uint32_t a) {
    asm volatile("ldmatrix.sync.aligned.m8n8.x4.shared.b16 {%0,%1,%2,%3}, [%4];"
                 : "=r"(r0), "=r"(r1), "=r"(r2), "=r"(r3) : "r"(a));
}
static __device__ __forceinline__ void mma16816(float* d, const uint32_t* a,
                                                uint32_t b0, uint32_t b1) {
    asm volatile(
        "mma.sync.aligned.m16n8k16.row.col.f32.bf16.bf16.f32 "
        "{%0,%1,%2,%3}, {%4,%5,%6,%7}, {%8,%9}, {%0,%1,%2,%3};"
        : "+f"(d[0]), "+f"(d[1]), "+f"(d[2]), "+f"(d[3])
        : "r"(a[0]), "r"(a[1]), "r"(a[2]), "r"(a[3]), "r"(b0), "r"(b1));
}

// ============================================================================
// Kernel 1: L2-normalize rows, convert to bf16, copy labels. One warp per row.
// ============================================================================
__global__ void prep_kernel(const float* __restrict__ feats,
                            const float* __restrict__ posf,
                            const int* __restrict__ labels) {
    int row  = blockIdx.x * 8 + (threadIdx.x >> 5);
    int lane = threadIdx.x & 31;
    const float* src = (row < B_HALF) ? (feats + (size_t)row * D_DIM)
                                      : (posf + (size_t)(row - B_HALF) * D_DIM);
    const float4* s4 = reinterpret_cast<const float4*>(src);
    float4 v0 = s4[lane];
    float4 v1 = s4[lane + 32];
    float ss = v0.x*v0.x + v0.y*v0.y + v0.z*v0.z + v0.w*v0.w
             + v1.x*v1.x + v1.y*v1.y + v1.z*v1.z + v1.w*v1.w;
    #pragma unroll
    for (int off = 16; off > 0; off >>= 1)
        ss += __shfl_xor_sync(0xffffffffu, ss, off);
    float inv = rsqrtf(ss);
    uint2 o0, o1;
    o0.x = pack_bf2(v0.x * inv, v0.y * inv);
    o0.y = pack_bf2(v0.z * inv, v0.w * inv);
    o1.x = pack_bf2(v1.x * inv, v1.y * inv);
    o1.y = pack_bf2(v1.z * inv, v1.w * inv);
    uint2* dst = reinterpret_cast<uint2*>(g_bf + (size_t)row * D_DIM);
    dst[lane]      = o0;
    dst[lane + 32] = o1;
    if (lane == 0)
        lab_buf[row] = labels[(row < B_HALF) ? row : row - B_HALF];
}

// issue async copy of one 128x256 bf16 tile into smem (row stride 528B)
static __device__ __forceinline__ void issue_tile(uint32_t sbuf, int row0, int tid) {
    const uint4* src = reinterpret_cast<const uint4*>(g_bf);
    #pragma unroll
    for (int t = 0; t < 16; t++) {
        int id = tid + t * 256;
        int r  = id >> 5;
        int kc = id & 31;
        cp16(sbuf + r * ROW_BYTES + kc * 16, src + (size_t)(row0 + r) * 32 + kc);
    }
}

// ============================================================================
// Kernel 2: HMMA gram + fused exp/masked row-sum epilogue.
// Grid = 128 CTAs (64 row-tiles x 2 halves), 256 threads (8 warps).
// Warp tile 64x32: wm = wid>>2 (2), wn = wid&3 (4).
// ============================================================================
__global__ void __launch_bounds__(256, 1) milnce_mma_kernel() {
    extern __shared__ char smem[];
    const uint32_t sb = smem_u32(smem);

    const int tid  = threadIdx.x;
    const int wid  = tid >> 5;
    const int lane = tid & 31;
    const int wm   = wid >> 2;          // 0..1
    const int wn   = wid & 3;           // 0..3
    const int rt   = blockIdx.x >> 1;
    const int half = blockIdx.x & 1;
    const int i0   = rt * TILE_M;
    const int jhb  = half * (NJ_HALF * TILE_N);

    // ldmatrix lane address pattern
    const int lrow16 = (lane & 7) + ((lane >> 3) & 1) * 8;   // row within 16
    const int lkb    = (lane >> 4) * 16;                     // 0 or 16 bytes

    const uint32_t a_lane = sb + A_OFF + (uint32_t)((wm * 64 + lrow16) * ROW_BYTES + lkb);
    const uint32_t b_lane_off = (uint32_t)((wn * 32 + lrow16) * ROW_BYTES + lkb);

    // prologue: A + B0, then B1
    issue_tile(sb + A_OFF, i0, tid);
    issue_tile(sb + B0_OFF, jhb + 0 * TILE_N, tid);
    CP_COMMIT();
    issue_tile(sb + B1_OFF, jhb + 1 * TILE_N, tid);
    CP_COMMIT();
    CP_WAIT(1);
    __syncthreads();

    // fixed row slots: slot = ms*2 + rh ; row = i0 + wm*64 + ms*16 + rh*8 + (lane>>2)
    int labr[8];
    #pragma unroll
    for (int s = 0; s < 8; s++)
        labr[s] = lab_buf[i0 + wm * 64 + (s >> 1) * 16 + (s & 1) * 8 + (lane >> 2)];

    float sall[8] = {0,0,0,0,0,0,0,0};
    float spos[8] = {0,0,0,0,0,0,0,0};

    const float K_EXP = 14.42695040888963f;   // log2(e)/tau

    #pragma unroll 1
    for (int jt = 0; jt < NJ_HALF; jt++) {
        const uint32_t bbuf = sb + ((jt & 1) ? B1_OFF : B0_OFF);
        const int jbase = jhb + jt * TILE_N;

        float acc[4][4][4];
        #pragma unroll
        for (int ms = 0; ms < 4; ms++)
            #pragma unroll
            for (int ns = 0; ns < 4; ns++)
                #pragma unroll
                for (int c = 0; c < 4; c++) acc[ms][ns][c] = 0.f;

        // column labels for this tile (fixed per thread): 4 ns x 2 cols
        int labc[4][2];
        #pragma unroll
        for (int ns = 0; ns < 4; ns++) {
            int c0 = jbase + wn * 32 + ns * 8 + (lane & 3) * 2;
            labc[ns][0] = lab_buf[c0];
            labc[ns][1] = lab_buf[c0 + 1];
        }

        #pragma unroll 2
        for (int ks = 0; ks < K_STEPS; ks++) {
            const uint32_t koff = (uint32_t)(ks * 32);
            uint32_t a[4][4];
            #pragma unroll
            for (int ms = 0; ms < 4; ms++)
                ldsm_x4(a[ms][0], a[ms][1], a[ms][2], a[ms][3],
                        a_lane + (uint32_t)(ms * 16 * ROW_BYTES) + koff);
            uint32_t b[2][4];
            #pragma unroll
            for (int p = 0; p < 2; p++)
                ldsm_x4(b[p][0], b[p][1], b[p][2], b[p][3],
                        bbuf + b_lane_off + (uint32_t)(p * 16 * ROW_BYTES) + koff);
            // b pair p covers n-subtiles 2p (frag {b0,b2}) and 2p+1 (frag {b1,b3})
            #pragma unroll
            for (int ms = 0; ms < 4; ms++) {
                mma16816(acc[ms][0], a[ms], b[0][0], b[0][2]);
                mma16816(acc[ms][1], a[ms], b[0][1], b[0][3]);
                mma16816(acc[ms][2], a[ms], b[1][0], b[1][2]);
                mma16816(acc[ms][3], a[ms], b[1][1], b[1][3]);
            }
        }

        // epilogue: exp + diag/label masked accumulation (rows fixed per slot)
        #pragma unroll
        for (int ms = 0; ms < 4; ms++) {
            const int gi_lo = i0 + wm * 64 + ms * 16 + (lane >> 2);
            #pragma unroll
            for (int ns = 0; ns < 4; ns++) {
                const int gj0 = jbase + wn * 32 + ns * 8 + (lane & 3) * 2;
                #pragma unroll
                for (int c = 0; c < 4; c++) {
                    const int rh  = c >> 1;          // 0: rows r, 1: rows r+8
                    const int gj  = gj0 + (c & 1);
                    const int gi  = gi_lo + rh * 8;
                    float e = ex2f(acc[ms][ns][c] * K_EXP);
                    if (gi != gj) {
                        const int slot = ms * 2 + rh;
                        sall[slot] += e;
                        if (labc[ns][c & 1] == labr[slot]) spos[slot] += e;
                    }
                }
            }
        }

        __syncthreads();   // everyone done reading current B buffer
        if (jt < NJ_HALF - 2) {
            issue_tile(bbuf, jhb + (jt + 2) * TILE_N, tid);
            CP_COMMIT();
            CP_WAIT(1);
        } else if (jt == NJ_HALF - 2) {
            CP_WAIT(0);
        }
        __syncthreads();
    }

    // ---- reduction: quad shfl -> smem cross-warp -> global ----
    #pragma unroll
    for (int s = 0; s < 8; s++) {
        sall[s] += __shfl_xor_sync(0xffffffffu, sall[s], 1);
        sall[s] += __shfl_xor_sync(0xffffffffu, sall[s], 2);
        spos[s] += __shfl_xor_sync(0xffffffffu, spos[s], 1);
        spos[s] += __shfl_xor_sync(0xffffffffu, spos[s], 2);
    }
    float* red_all = reinterpret_cast<float*>(smem + RED_OFF);          // [128][4]
    float* red_pos = red_all + 128 * 4;                                 // [128][4]
    __syncthreads();   // done with B buffers / safe to reuse nothing; just order red writes
    if ((lane & 3) == 0) {
        #pragma unroll
        for (int s = 0; s < 8; s++) {
            int rloc = wm * 64 + (s >> 1) * 16 + (s & 1) * 8 + (lane >> 2);
            red_all[rloc * 4 + wn] = sall[s];
            red_pos[rloc * 4 + wn] = spos[s];
        }
    }
    __syncthreads();
    if (tid < 128) {
        float a = red_all[tid * 4 + 0] + red_all[tid * 4 + 1]
                + red_all[tid * 4 + 2] + red_all[tid * 4 + 3];
        float p = red_pos[tid * 4 + 0] + red_pos[tid * 4 + 1]
                + red_pos[tid * 4 + 2] + red_pos[tid * 4 + 3];
        part_all[half][i0 + tid] = a;
        part_pos[half][i0 + tid] = p;
    }
}

// ============================================================================
// Kernel 3: loss = sum_i [ log(S_all_i) - log(S_pos_i) ]
// ============================================================================
__global__ void finalize_kernel(float* __restrict__ out) {
    __shared__ float red[256];
    float s = 0.f;
    for (int i = threadIdx.x; i < N_TOT; i += 256) {
        float a = part_all[0][i] + part_all[1][i];
        float p = part_pos[0][i] + part_pos[1][i];
        s += logf(a) - logf(p);
    }
    red[threadIdx.x] = s;
    __syncthreads();
    for (int o = 128; o > 0; o >>= 1) {
        if (threadIdx.x < o) red[threadIdx.x] += red[threadIdx.x + o];
        __syncthreads();
    }
    if (threadIdx.x == 0) out[0] = red[0];
}

// ============================================================================
extern "C" void kernel_launch(void* const* d_in, const int* in_sizes, int n_in,
                              void* d_out, int out_size) {
    const float* feats  = (const float*)d_in[0];
    const float* posf   = (const float*)d_in[1];
    const int*   labels = (const int*)d_in[2];

    prep_kernel<<<N_TOT / 8, 256>>>(feats, posf, labels);

    cudaFuncSetAttribute(milnce_mma_kernel,
                         cudaFuncAttributeMaxDynamicSharedMemorySize, SMEM_TOTAL);
    milnce_mma_kernel<<<128, 256, SMEM_TOTAL>>>();

    finalize_kernel<<<1, 256>>>((float*)d_out);
}

// round 5
// speedup vs baseline: 6.8793x; 1.0025x over previous
#include <cuda_runtime.h>
#include <cuda_bf16.h>
#include <cstdint>

#define N_TOT   8192
#define D_DIM   256
#define B_HALF  4096
#define TILE_M  128
#define TILE_N  128
#define NJ_HALF 32                 // column tiles per half
#define K_STEPS 16                 // 256 / 16

#define ROW_BYTES 528              // 264 bf16: pad to kill ldmatrix bank conflicts
#define A_OFF   0
#define B0_OFF  (TILE_M * ROW_BYTES)                 // 67584
#define B1_OFF  (B0_OFF + TILE_M * ROW_BYTES)        // 135168
#define RED_OFF (B1_OFF + TILE_M * ROW_BYTES)        // 202752
#define SMEM_TOTAL (RED_OFF + 128 * 4 * 2 * 4)       // 206848

// -------- device scratch --------
__device__ __align__(16) __nv_bfloat16 g_bf[N_TOT * D_DIM];   // normalized bf16 (4 MB)
__device__ int   lab_buf[N_TOT];
__device__ float part_all[2][N_TOT];
__device__ float part_pos[2][N_TOT];

// ======================= helpers =======================
static __device__ __forceinline__ uint32_t smem_u32(const void* p) {
    uint32_t a;
    asm("{ .reg .u64 t; cvta.to.shared.u64 t, %1; cvt.u32.u64 %0, t; }" : "=r"(a) : "l"(p));
    return a;
}
static __device__ __forceinline__ float ex2f(float x) {
    float r; asm("ex2.approx.ftz.f32 %0, %1;" : "=f"(r) : "f"(x)); return r;
}
static __device__ __forceinline__ uint32_t pack_bf2(float lo, float hi) {
    uint32_t r; asm("cvt.rn.bf16x2.f32 %0, %1, %2;" : "=r"(r) : "f"(hi), "f"(lo)); return r;
}
static __device__ __forceinline__ void cp16(uint32_t saddr, const void* g) {
    asm volatile("cp.async.cg.shared.global [%0], [%1], 16;" :: "r"(saddr), "l"(g) : "memory");
}
#define CP_COMMIT() asm volatile("cp.async.commit_group;" ::: "memory")
#define CP_WAIT(n)  asm volatile("cp.async.wait_group %0;" :: "n"(n) : "memory")

static __device__ __forceinline__ void ldsm_x4(uint32_t& r0, uint32_t& r1,
                                               uint32_t& r2, uint32_t& r3, uint32_t a) {
    asm volatile("ldmatrix.sync.aligned.m8n8.x4.shared.b16 {%0,%1,%2,%3}, [%4];"
                 : "=r"(r0), "=r"(r1), "=r"(r2), "=r"(r3) : "r"(a));
}
static __device__ __forceinline__ void mma16816(float* d, const uint32_t* a,
                                                uint32_t b0, uint32_t b1) {
    asm volatile(
        "mma.sync.aligned.m16n8k16.row.col.f32.bf16.bf16.f32 "
        "{%0,%1,%2,%3}, {%4,%5,%6,%7}, {%8,%9}, {%0,%1,%2,%3};"
        : "+f"(d[0]), "+f"(d[1]), "+f"(d[2]), "+f"(d[3])
        : "r"(a[0]), "r"(a[1]), "r"(a[2]), "r"(a[3]), "r"(b0), "r"(b1));
}

// ============================================================================
// Kernel 1: L2-normalize rows, convert to bf16, copy labels. One warp per row.
// ============================================================================
__global__ void prep_kernel(const float* __restrict__ feats,
                            const float* __restrict__ posf,
                            const int* __restrict__ labels) {
    int row  = blockIdx.x * 8 + (threadIdx.x >> 5);
    int lane = threadIdx.x & 31;
    const float* src = (row < B_HALF) ? (feats + (size_t)row * D_DIM)
                                      : (posf + (size_t)(row - B_HALF) * D_DIM);
    const float4* s4 = reinterpret_cast<const float4*>(src);
    float4 v0 = s4[lane];
    float4 v1 = s4[lane + 32];
    float ss = v0.x*v0.x + v0.y*v0.y + v0.z*v0.z + v0.w*v0.w
             + v1.x*v1.x + v1.y*v1.y + v1.z*v1.z + v1.w*v1.w;
    #pragma unroll
    for (int off = 16; off > 0; off >>= 1)
        ss += __shfl_xor_sync(0xffffffffu, ss, off);
    float inv = rsqrtf(ss);
    uint2 o0, o1;
    o0.x = pack_bf2(v0.x * inv, v0.y * inv);
    o0.y = pack_bf2(v0.z * inv, v0.w * inv);
    o1.x = pack_bf2(v1.x * inv, v1.y * inv);
    o1.y = pack_bf2(v1.z * inv, v1.w * inv);
    uint2* dst = reinterpret_cast<uint2*>(g_bf + (size_t)row * D_DIM);
    dst[lane]      = o0;
    dst[lane + 32] = o1;
    if (lane == 0)
        lab_buf[row] = labels[(row < B_HALF) ? row : row - B_HALF];
}

// issue async copy of one 128x256 bf16 tile into smem (row stride 528B)
static __device__ __forceinline__ void issue_tile(uint32_t sbuf, int row0, int tid) {
    const uint4* src = reinterpret_cast<const uint4*>(g_bf);
    #pragma unroll
    for (int t = 0; t < 16; t++) {
        int id = tid + t * 256;
        int r  = id >> 5;
        int kc = id & 31;
        cp16(sbuf + r * ROW_BYTES + kc * 16, src + (size_t)(row0 + r) * 32 + kc);
    }
}

// ============================================================================
// MMA for one 128x128 tile into the given acc set (zeroed here).
// ============================================================================
static __device__ __forceinline__ void mma_tile(float (&acc)[4][4][4],
                                                uint32_t a_lane, uint32_t b_lane) {
    #pragma unroll
    for (int ms = 0; ms < 4; ms++)
        #pragma unroll
        for (int ns = 0; ns < 4; ns++)
            #pragma unroll
            for (int c = 0; c < 4; c++) acc[ms][ns][c] = 0.f;

    #pragma unroll 2
    for (int ks = 0; ks < K_STEPS; ks++) {
        const uint32_t koff = (uint32_t)(ks * 32);
        uint32_t a[4][4];
        #pragma unroll
        for (int ms = 0; ms < 4; ms++)
            ldsm_x4(a[ms][0], a[ms][1], a[ms][2], a[ms][3],
                    a_lane + (uint32_t)(ms * 16 * ROW_BYTES) + koff);
        uint32_t b[2][4];
        #pragma unroll
        for (int p = 0; p < 2; p++)
            ldsm_x4(b[p][0], b[p][1], b[p][2], b[p][3],
                    b_lane + (uint32_t)(p * 16 * ROW_BYTES) + koff);
        #pragma unroll
        for (int ms = 0; ms < 4; ms++) {
            mma16816(acc[ms][0], a[ms], b[0][0], b[0][2]);
            mma16816(acc[ms][1], a[ms], b[0][1], b[0][3]);
            mma16816(acc[ms][2], a[ms], b[1][0], b[1][2]);
            mma16816(acc[ms][3], a[ms], b[1][1], b[1][3]);
        }
    }
}

// ============================================================================
// Epilogue: exp + (diag)/label masked accumulation for one finished tile.
// ============================================================================
template <bool DIAG>
static __device__ __forceinline__ void epilogue(const float (&acc)[4][4][4],
        int i0, int wm, int wn, int lane, int jbase,
        const int (&labr)[8], float (&sall)[8], float (&spos)[8]) {
    const float K_EXP = 14.42695040888963f;   // log2(e)/tau
    int labc[4][2];
    #pragma unroll
    for (int ns = 0; ns < 4; ns++) {
        int c0 = jbase + wn * 32 + ns * 8 + (lane & 3) * 2;
        labc[ns][0] = lab_buf[c0];
        labc[ns][1] = lab_buf[c0 + 1];
    }
    #pragma unroll
    for (int ms = 0; ms < 4; ms++) {
        const int gi_lo = i0 + wm * 64 + ms * 16 + (lane >> 2);
        #pragma unroll
        for (int ns = 0; ns < 4; ns++) {
            const int gj0 = jbase + wn * 32 + ns * 8 + (lane & 3) * 2;
            #pragma unroll
            for (int c = 0; c < 4; c++) {
                const int rh   = c >> 1;
                const int slot = ms * 2 + rh;
                float e = ex2f(acc[ms][ns][c] * K_EXP);
                bool ok = true;
                if (DIAG) ok = (gi_lo + rh * 8) != (gj0 + (c & 1));
                if (ok) {
                    sall[slot] += e;
                    if (labc[ns][c & 1] == labr[slot]) spos[slot] += e;
                }
            }
        }
    }
}

// ============================================================================
// Kernel 2: HMMA gram, software-pipelined: MMA(tile jt) overlaps epilogue(jt-1).
// Grid = 128 CTAs (64 row-tiles x 2 halves), 256 threads (8 warps).
// ============================================================================
__global__ void __launch_bounds__(256, 1) milnce_mma_kernel() {
    extern __shared__ char smem[];
    const uint32_t sb = smem_u32(smem);

    const int tid  = threadIdx.x;
    const int wid  = tid >> 5;
    const int lane = tid & 31;
    const int wm   = wid >> 2;          // 0..1
    const int wn   = wid & 3;           // 0..3
    const int rt   = blockIdx.x >> 1;
    const int half = blockIdx.x & 1;
    const int i0   = rt * TILE_M;
    const int jhb  = half * (NJ_HALF * TILE_N);

    const int lrow16 = (lane & 7) + ((lane >> 3) & 1) * 8;
    const int lkb    = (lane >> 4) * 16;

    const uint32_t a_lane = sb + A_OFF + (uint32_t)((wm * 64 + lrow16) * ROW_BYTES + lkb);
    const uint32_t b_off  = (uint32_t)((wn * 32 + lrow16) * ROW_BYTES + lkb);
    const uint32_t b0_lane = sb + B0_OFF + b_off;
    const uint32_t b1_lane = sb + B1_OFF + b_off;

    // prologue: A + B0 (group 0), B1 (group 1)
    issue_tile(sb + A_OFF, i0, tid);
    issue_tile(sb + B0_OFF, jhb + 0 * TILE_N, tid);
    CP_COMMIT();
    issue_tile(sb + B1_OFF, jhb + 1 * TILE_N, tid);
    CP_COMMIT();

    int labr[8];
    #pragma unroll
    for (int s = 0; s < 8; s++)
        labr[s] = lab_buf[i0 + wm * 64 + (s >> 1) * 16 + (s & 1) * 8 + (lane >> 2)];

    float sall[8] = {0,0,0,0,0,0,0,0};
    float spos[8] = {0,0,0,0,0,0,0,0};

    float accA[4][4][4], accB[4][4][4];

    // ---- iter 0: MMA tile 0 into accA (no epilogue yet) ----
    CP_WAIT(1);
    __syncthreads();
    mma_tile(accA, a_lane, b0_lane);
    __syncthreads();
    issue_tile(sb + B0_OFF, jhb + 2 * TILE_N, tid);
    CP_COMMIT();

    // ---- steady state: pairs (1,2),(3,4),...,(29,30) ----
    #pragma unroll 1
    for (int jt = 1; jt < NJ_HALF - 1; jt += 2) {
        // odd tile jt -> accB ; epilogue tile jt-1 from accA
        CP_WAIT(1);
        __syncthreads();
        mma_tile(accB, a_lane, b1_lane);
        __syncthreads();
        if (jt + 2 < NJ_HALF) { issue_tile(sb + B1_OFF, jhb + (jt + 2) * TILE_N, tid); CP_COMMIT(); }
        {
            const int jb = jhb + (jt - 1) * TILE_N;
            if (jb == i0) epilogue<true >(accA, i0, wm, wn, lane, jb, labr, sall, spos);
            else          epilogue<false>(accA, i0, wm, wn, lane, jb, labr, sall, spos);
        }
        // even tile jt+1 -> accA ; epilogue tile jt from accB
        CP_WAIT(1);
        __syncthreads();
        mma_tile(accA, a_lane, b0_lane);
        __syncthreads();
        if (jt + 3 < NJ_HALF) { issue_tile(sb + B0_OFF, jhb + (jt + 3) * TILE_N, tid); CP_COMMIT(); }
        {
            const int jb = jhb + jt * TILE_N;
            if (jb == i0) epilogue<true >(accB, i0, wm, wn, lane, jb, labr, sall, spos);
            else          epilogue<false>(accB, i0, wm, wn, lane, jb, labr, sall, spos);
        }
    }

    // ---- peel tile 31 ----
    CP_WAIT(0);
    __syncthreads();
    mma_tile(accB, a_lane, b1_lane);
    {
        const int jb = jhb + (NJ_HALF - 2) * TILE_N;   // tile 30 from accA
        if (jb == i0) epilogue<true >(accA, i0, wm, wn, lane, jb, labr, sall, spos);
        else          epilogue<false>(accA, i0, wm, wn, lane, jb, labr, sall, spos);
    }
    {
        const int jb = jhb + (NJ_HALF - 1) * TILE_N;   // tile 31 from accB
        if (jb == i0) epilogue<true >(accB, i0, wm, wn, lane, jb, labr, sall, spos);
        else          epilogue<false>(accB, i0, wm, wn, lane, jb, labr, sall, spos);
    }

    // ---- reduction: quad shfl -> smem cross-warp -> global ----
    #pragma unroll
    for (int s = 0; s < 8; s++) {
        sall[s] += __shfl_xor_sync(0xffffffffu, sall[s], 1);
        sall[s] += __shfl_xor_sync(0xffffffffu, sall[s], 2);
        spos[s] += __shfl_xor_sync(0xffffffffu, spos[s], 1);
        spos[s] += __shfl_xor_sync(0xffffffffu, spos[s], 2);
    }
    float* red_all = reinterpret_cast<float*>(smem + RED_OFF);          // [128][4]
    float* red_pos = red_all + 128 * 4;                                 // [128][4]
    __syncthreads();
    if ((lane & 3) == 0) {
        #pragma unroll
        for (int s = 0; s < 8; s++) {
            int rloc = wm * 64 + (s >> 1) * 16 + (s & 1) * 8 + (lane >> 2);
            red_all[rloc * 4 + wn] = sall[s];
            red_pos[rloc * 4 + wn] = spos[s];
        }
    }
    __syncthreads();
    if (tid < 128) {
        float a = red_all[tid * 4 + 0] + red_all[tid * 4 + 1]
                + red_all[tid * 4 + 2] + red_all[tid * 4 + 3];
        float p = red_pos[tid * 4 + 0] + red_pos[tid * 4 + 1]
                + red_pos[tid * 4 + 2] + red_pos[tid * 4 + 3];
        part_all[half][i0 + tid] = a;
        part_pos[half][i0 + tid] = p;
    }
}

// ============================================================================
// Kernel 3: loss = sum_i [ log(S_all_i) - log(S_pos_i) ]
// ============================================================================
__global__ void finalize_kernel(float* __restrict__ out) {
    __shared__ float red[256];
    float s = 0.f;
    for (int i = threadIdx.x; i < N_TOT; i += 256) {
        float a = part_all[0][i] + part_all[1][i];
        float p = part_pos[0][i] + part_pos[1][i];
        s += logf(a) - logf(p);
    }
    red[threadIdx.x] = s;
    __syncthreads();
    for (int o = 128; o > 0; o >>= 1) {
        if (threadIdx.x < o) red[threadIdx.x] += red[threadIdx.x + o];
        __syncthreads();
    }
    if (threadIdx.x == 0) out[0] = red[0];
}

// ============================================================================
extern "C" void kernel_launch(void* const* d_in, const int* in_sizes, int n_in,
                              void* d_out, int out_size) {
    const float* feats  = (const float*)d_in[0];
    const float* posf   = (const float*)d_in[1];
    const int*   labels = (const int*)d_in[2];

    prep_kernel<<<N_TOT / 8, 256>>>(feats, posf, labels);

    cudaFuncSetAttribute(milnce_mma_kernel,
                         cudaFuncAttributeMaxDynamicSharedMemorySize, SMEM_TOTAL);
    milnce_mma_kernel<<<128, 256, SMEM_TOTAL>>>();

    finalize_kernel<<<1, 256>>>((float*)d_out);
}